// round 16
// baseline (speedup 1.0000x reference)
#include <cuda_runtime.h>
#include <cuda_fp16.h>

// ---------------------------------------------------------------------------
// Problem constants
// ---------------------------------------------------------------------------
#define Bn  4
#define Sn  1024
#define Dn  1024
#define Hn  16
#define DKn 64

// ---------------------------------------------------------------------------
// Device scratch (everything on the mma path stored fp16)
// ---------------------------------------------------------------------------
__device__ __half g_q[(size_t)Bn * Hn * Sn * DKn];     // [B,H,S,DK] (pre-scaled by 0.125)
__device__ __half g_k[(size_t)Bn * Hn * Sn * DKn];
__device__ __half g_v[(size_t)Bn * Hn * Sn * DKn];
__device__ __half g_biasT[(size_t)Bn * Hn * Sn * Sn];  // [B,H,S,S] fp16, mask+scale folded
__device__ __half g_ctx[(size_t)Bn * Sn * Dn];         // [B,S,D] fp16
__device__ __half g_xq[(size_t)Bn * Sn * Dn];          // fp16 inputs
__device__ __half g_xk[(size_t)Bn * Sn * Dn];
__device__ __half g_xv[(size_t)Bn * Sn * Dn];
__device__ __half g_wq[(size_t)Dn * Dn];               // fp16 weights
__device__ __half g_wk[(size_t)Dn * Dn];
__device__ __half g_wv[(size_t)Dn * Dn];
__device__ __half g_wo[(size_t)Dn * Dn];
__device__ unsigned char g_mask[Bn * Sn];

// ---------------------------------------------------------------------------
// Helpers
// ---------------------------------------------------------------------------
__device__ __forceinline__ unsigned h2u(__half2 h) {
    return *reinterpret_cast<unsigned*>(&h);
}

__device__ __forceinline__ unsigned smaddr(const void* p) {
    return (unsigned)__cvta_generic_to_shared(p);
}

__device__ __forceinline__ void ldsm4(unsigned& r0, unsigned& r1, unsigned& r2,
                                      unsigned& r3, unsigned addr) {
    asm volatile("ldmatrix.sync.aligned.m8n8.x4.shared.b16 {%0,%1,%2,%3}, [%4];"
                 : "=r"(r0), "=r"(r1), "=r"(r2), "=r"(r3) : "r"(addr));
}

__device__ __forceinline__ void ldsm4t(unsigned& r0, unsigned& r1, unsigned& r2,
                                       unsigned& r3, unsigned addr) {
    asm volatile("ldmatrix.sync.aligned.m8n8.x4.trans.shared.b16 {%0,%1,%2,%3}, [%4];"
                 : "=r"(r0), "=r"(r1), "=r"(r2), "=r"(r3) : "r"(addr));
}

__device__ __forceinline__ void mma_f16(float c[4], const unsigned a[4],
                                        unsigned b0, unsigned b1) {
    asm volatile(
        "mma.sync.aligned.m16n8k16.row.col.f32.f16.f16.f32 "
        "{%0,%1,%2,%3},{%4,%5,%6,%7},{%8,%9},{%0,%1,%2,%3};\n"
        : "+f"(c[0]), "+f"(c[1]), "+f"(c[2]), "+f"(c[3])
        : "r"(a[0]), "r"(a[1]), "r"(a[2]), "r"(a[3]), "r"(b0), "r"(b1));
}

__device__ __forceinline__ void cpa16(unsigned dst, const void* src) {
    asm volatile("cp.async.cg.shared.global [%0], [%1], 16;"
                 :: "r"(dst), "l"(src) : "memory");
}

#define CPA_COMMIT() asm volatile("cp.async.commit_group;" ::: "memory")
#define CPA_WAIT(n)  asm volatile("cp.async.wait_group %0;" :: "n"(n) : "memory")

// ---------------------------------------------------------------------------
// fp32 -> fp16 conversion for inputs + weights; z==7 also normalizes the mask
// ---------------------------------------------------------------------------
__global__ void f2h_kernel(const float* __restrict__ xq, const float* __restrict__ xk,
                           const float* __restrict__ xv, const float* __restrict__ wq,
                           const float* __restrict__ wk, const float* __restrict__ wv,
                           const float* __restrict__ wo, const void* __restrict__ mraw) {
    int z = blockIdx.z;
    if (z == 7) {
        if (blockIdx.x != 0) return;
        __shared__ int flags[2];
        if (threadIdx.x < 2) flags[threadIdx.x] = 0;
        __syncthreads();
        const unsigned* w = (const unsigned*)mraw;
        for (int i = threadIdx.x; i < 1024; i += blockDim.x) {
            unsigned v = w[i];
            if (v > 1u) flags[0] = 1;
            if (v != 0u && v != 0x3F800000u) flags[1] = 1;
        }
        __syncthreads();
        int mode = flags[0] ? (flags[1] ? 0 : 2) : 1;
        for (int i = threadIdx.x; i < Bn * Sn; i += blockDim.x) {
            unsigned char v;
            if (mode == 1)      v = (((const int*)mraw)[i] != 0);
            else if (mode == 2) v = (((const float*)mraw)[i] != 0.f);
            else                v = (((const unsigned char*)mraw)[i] != 0);
            g_mask[i] = v;
        }
        return;
    }
    const float* src;
    __half* dst;
    int n4;
    switch (z) {
        case 0: src = xq; dst = g_xq; n4 = (Bn * Sn * Dn) / 4; break;
        case 1: src = xk; dst = g_xk; n4 = (Bn * Sn * Dn) / 4; break;
        case 2: src = xv; dst = g_xv; n4 = (Bn * Sn * Dn) / 4; break;
        case 3: src = wq; dst = g_wq; n4 = (Dn * Dn) / 4; break;
        case 4: src = wk; dst = g_wk; n4 = (Dn * Dn) / 4; break;
        case 5: src = wv; dst = g_wv; n4 = (Dn * Dn) / 4; break;
        default: src = wo; dst = g_wo; n4 = (Dn * Dn) / 4; break;
    }
    for (int i = blockIdx.x * blockDim.x + threadIdx.x; i < n4;
         i += gridDim.x * blockDim.x) {
        float4 v = ((const float4*)src)[i];
        ((uint2*)dst)[i] = make_uint2(h2u(__floats2half2_rn(v.x, v.y)),
                                      h2u(__floats2half2_rn(v.z, v.w)));
    }
}

// ---------------------------------------------------------------------------
// Bias transpose [B,S,S,H] fp32 -> [B,H,S,S] fp16, with the k-mask and the
// 1/sqrt(dk)=0.125 scale folded in:
//   biasM[b,h,q,k] = maskK[b,k] ? bias*0.125 : -30000
// (-30000: after adding scores ~O(15) the exp underflows to exactly 0 weight,
//  matching the reference's -1e9 semantics for valid q rows.)
// Runs after f2h (g_mask ready).
// ---------------------------------------------------------------------------
__global__ void bias_tr_kernel(const float* __restrict__ bias) {
    __shared__ float t[16][129];
    const int k0 = blockIdx.x * 128;
    const int q  = blockIdx.y;
    const int b  = blockIdx.z;
    const float* src = bias + ((size_t)(b * Sn + q) * Sn + k0) * Hn;
    for (int i = threadIdx.x; i < 2048; i += 256) {
        int kk = i >> 4, hh = i & 15;
        t[hh][kk] = __ldcs(src + i);
    }
    __syncthreads();
    for (int i = threadIdx.x; i < 1024; i += 256) {
        int hh = i >> 6, kk2 = i & 63;
        int kg = k0 + kk2 * 2;
        float m0 = g_mask[b * Sn + kg]     ? 1.f : 0.f;
        float m1 = g_mask[b * Sn + kg + 1] ? 1.f : 0.f;
        float v0 = m0 ? t[hh][kk2 * 2] * 0.125f     : -30000.f;
        float v1 = m1 ? t[hh][kk2 * 2 + 1] * 0.125f : -30000.f;
        __half2 v = __floats2half2_rn(v0, v1);
        __half* dst = &g_biasT[((size_t)(b * Hn + hh) * Sn + q) * Sn + kg];
        __stcs((__half2*)dst, v);
    }
}

// ---------------------------------------------------------------------------
// TN GEMM fp16 (R15): 128x128x32 tile, 256 threads, 8 warps (2m x 4n),
// 2-stage cp.async pipeline, ONE __syncthreads per k-tile.
// oscale multiplies the final (acc + bias) — used to pre-scale Q by 0.125.
// ---------------------------------------------------------------------------
#define GSH 40   // smem stride in halves (80B rows: ldmatrix conflict-free)

template <int MODE>
__device__ __forceinline__ void gemm_h16(const __half* __restrict__ A,
                                         const __half* __restrict__ W,
                                         const float* __restrict__ bvec,
                                         void* __restrict__ outv,
                                         float oscale) {
    __shared__ __half sA[2][128 * GSH];
    __shared__ __half sW[2][128 * GSH];

    const int tid  = threadIdx.x;
    const int lane = tid & 31;
    const int warp = tid >> 5;
    const int wm = (warp >> 2) * 64;
    const int wn = (warp & 3) * 32;
    const int m0 = blockIdx.y * 128;
    const int n0 = blockIdx.x * 128;

    float acc[4][4][4];
#pragma unroll
    for (int mt = 0; mt < 4; mt++)
#pragma unroll
        for (int nt = 0; nt < 4; nt++)
#pragma unroll
            for (int q = 0; q < 4; q++) acc[mt][nt][q] = 0.f;

#pragma unroll
    for (int i = 0; i < 2; i++) {
        int task = i * 256 + tid;
        int row = task >> 2, c8 = task & 3;
        cpa16(smaddr(&sA[0][row * GSH + c8 * 8]), A + (size_t)(m0 + row) * Dn + c8 * 8);
        cpa16(smaddr(&sW[0][row * GSH + c8 * 8]), W + (size_t)(n0 + row) * Dn + c8 * 8);
    }
    CPA_COMMIT();

    for (int kt = 0; kt < 32; kt++) {
        const int b = kt & 1;
        CPA_WAIT(0);
        __syncthreads();

        if (kt < 31) {
            const int kb = (kt + 1) * 32;
#pragma unroll
            for (int i = 0; i < 2; i++) {
                int task = i * 256 + tid;
                int row = task >> 2, c8 = task & 3;
                cpa16(smaddr(&sA[b ^ 1][row * GSH + c8 * 8]),
                      A + (size_t)(m0 + row) * Dn + kb + c8 * 8);
                cpa16(smaddr(&sW[b ^ 1][row * GSH + c8 * 8]),
                      W + (size_t)(n0 + row) * Dn + kb + c8 * 8);
            }
            CPA_COMMIT();
        }

        const __half* cA = sA[b];
        const __half* cW = sW[b];
#pragma unroll
        for (int ks = 0; ks < 2; ks++) {
            const int koff = ks * 16 + ((lane >> 4) << 3);
            unsigned afr[4][4];
#pragma unroll
            for (int mt = 0; mt < 4; mt++)
                ldsm4(afr[mt][0], afr[mt][1], afr[mt][2], afr[mt][3],
                      smaddr(&cA[(wm + mt * 16 + (lane & 15)) * GSH + koff]));
            unsigned bfr[4][2];
#pragma unroll
            for (int ntp = 0; ntp < 2; ntp++) {
                unsigned t0, t1, t2, t3;
                ldsm4(t0, t1, t2, t3,
                      smaddr(&cW[(wn + ntp * 16 + (lane & 7) + (((lane >> 4) & 1) << 3)) * GSH +
                                 ks * 16 + (((lane >> 3) & 1) << 3)]));
                bfr[2 * ntp][0] = t0; bfr[2 * ntp][1] = t1;
                bfr[2 * ntp + 1][0] = t2; bfr[2 * ntp + 1][1] = t3;
            }
#pragma unroll
            for (int mt = 0; mt < 4; mt++)
#pragma unroll
                for (int nt = 0; nt < 4; nt++)
                    mma_f16(acc[mt][nt], afr[mt], bfr[nt][0], bfr[nt][1]);
        }
    }

#pragma unroll
    for (int mt = 0; mt < 4; mt++) {
#pragma unroll
        for (int nt = 0; nt < 4; nt++) {
            int row = m0 + wm + mt * 16 + (lane >> 2);
            int col = n0 + wn + nt * 8 + ((lane & 3) << 1);
            float b0 = bvec[col], b1 = bvec[col + 1];
            float v00 = (acc[mt][nt][0] + b0) * oscale, v01 = (acc[mt][nt][1] + b1) * oscale;
            float v10 = (acc[mt][nt][2] + b0) * oscale, v11 = (acc[mt][nt][3] + b1) * oscale;
            if (MODE == 0) {
                float* out = (float*)outv;
                *(float2*)(out + (size_t)row * Dn + col) = make_float2(v00, v01);
                *(float2*)(out + (size_t)(row + 8) * Dn + col) = make_float2(v10, v11);
            } else {
                __half* out = (__half*)outv;
                int hh = col >> 6, dk = col & 63;
                int bb0 = row >> 10, s0 = row & 1023;
                int r8 = row + 8;
                int bb1 = r8 >> 10, s1 = r8 & 1023;
                *(__half2*)(out + ((size_t)(bb0 * Hn + hh) * Sn + s0) * DKn + dk) =
                    __floats2half2_rn(v00, v01);
                *(__half2*)(out + ((size_t)(bb1 * Hn + hh) * Sn + s1) * DKn + dk) =
                    __floats2half2_rn(v10, v11);
            }
        }
    }
}

__global__ void __launch_bounds__(256) qkv_proj_kernel(
    const float* __restrict__ bq, const float* __restrict__ bk,
    const float* __restrict__ bv) {
    int z = blockIdx.z;
    const __half* A = (z == 0) ? g_xq : (z == 1) ? g_xk : g_xv;
    const __half* W = (z == 0) ? g_wq : (z == 1) ? g_wk : g_wv;
    const float* bb = (z == 0) ? bq : (z == 1) ? bk : bv;
    __half* out = (z == 0) ? g_q : (z == 1) ? g_k : g_v;
    gemm_h16<1>(A, W, bb, out, (z == 0) ? 0.125f : 1.0f);
}

__global__ void __launch_bounds__(256) outproj_kernel(
    const float* __restrict__ bo, float* __restrict__ out) {
    gemm_h16<0>(g_ctx, g_wo, bo, out, 1.0f);
}

// ---------------------------------------------------------------------------
// Flash attention fp16 v5: 64 q-rows, 128 threads, 3 CTAs/SM.
//  - Q frags hoisted; P in registers (FA2); K/V cp.async double-buffered
//  - scale + k-mask pre-folded into Q / biasM: hot loop is v = mq ? s+b : 0
// ---------------------------------------------------------------------------
#define ASH 72   // smem stride in halves (144B rows: ldmatrix conflict-free)

__global__ void __launch_bounds__(128, 3) attn_kernel() {
    __shared__ __half sQ[64 * ASH];
    __shared__ __half sK[2][64 * ASH];
    __shared__ __half sV[2][64 * ASH];

    const int qt = blockIdx.x, h = blockIdx.y, b = blockIdx.z;
    const int q0 = qt * 64;
    const int tid = threadIdx.x, lane = tid & 31, warp = tid >> 5;
    const int rq = warp * 16 + (lane >> 2);

    const size_t headoff = (size_t)(b * Hn + h) * Sn * DKn;
    const __half* Qg = g_q + headoff + (size_t)q0 * DKn;
    const __half* Kg = g_k + headoff;
    const __half* Vg = g_v + headoff;
    const __half* Bg = g_biasT + ((size_t)(b * Hn + h) * Sn + q0) * Sn;
    const unsigned char* Mg = g_mask + b * Sn;

#pragma unroll
    for (int i = 0; i < 4; i++) {
        int task = i * 128 + tid;
        int row = task >> 3, c4 = task & 7;
        *(uint4*)&sQ[row * ASH + c4 * 8] = *(const uint4*)(Qg + (size_t)row * DKn + c4 * 8);
        cpa16(smaddr(&sK[0][row * ASH + c4 * 8]), Kg + (size_t)row * DKn + c4 * 8);
        cpa16(smaddr(&sV[0][row * ASH + c4 * 8]), Vg + (size_t)row * DKn + c4 * 8);
    }
    CPA_COMMIT();
    __syncthreads();
    unsigned qfr[4][4];
#pragma unroll
    for (int ks = 0; ks < 4; ks++)
        ldsm4(qfr[ks][0], qfr[ks][1], qfr[ks][2], qfr[ks][3],
              smaddr(&sQ[(warp * 16 + (lane & 15)) * ASH + ks * 16 + ((lane >> 4) << 3)]));

    const int mq0 = Mg[q0 + rq];
    const int mq1 = Mg[q0 + rq + 8];

    float mrow0 = -1e30f, mrow1 = -1e30f, lrow0 = 0.f, lrow1 = 0.f;
    float o[8][4];
#pragma unroll
    for (int nt = 0; nt < 8; nt++)
#pragma unroll
        for (int q = 0; q < 4; q++) o[nt][q] = 0.f;

    for (int kt = 0; kt < 16; kt++) {
        const int kv0 = kt * 64;
        const int buf = kt & 1;

        __half2 bb0[8], bb1[8];
#pragma unroll
        for (int nt = 0; nt < 8; nt++) {
            int col = kv0 + nt * 8 + ((lane & 3) << 1);
            bb0[nt] = __ldcs((const __half2*)(Bg + (size_t)rq * Sn + col));
            bb1[nt] = __ldcs((const __half2*)(Bg + (size_t)(rq + 8) * Sn + col));
        }

        CPA_WAIT(0);
        __syncthreads();  // tile kt resident; reads of buf^1 (kt-1) retired

        if (kt < 15) {
            const int kb = kv0 + 64;
#pragma unroll
            for (int i = 0; i < 4; i++) {
                int task = i * 128 + tid;
                int row = task >> 3, c4 = task & 7;
                cpa16(smaddr(&sK[buf ^ 1][row * ASH + c4 * 8]),
                      Kg + (size_t)(kb + row) * DKn + c4 * 8);
                cpa16(smaddr(&sV[buf ^ 1][row * ASH + c4 * 8]),
                      Vg + (size_t)(kb + row) * DKn + c4 * 8);
            }
            CPA_COMMIT();
        }

        // S = Q K^T  (Q pre-scaled by 0.125)
        float s[8][4];
#pragma unroll
        for (int nt = 0; nt < 8; nt++)
#pragma unroll
            for (int q = 0; q < 4; q++) s[nt][q] = 0.f;

#pragma unroll
        for (int ks = 0; ks < 4; ks++) {
#pragma unroll
            for (int ntp = 0; ntp < 4; ntp++) {
                unsigned t0, t1, t2, t3;
                ldsm4(t0, t1, t2, t3,
                      smaddr(&sK[buf][(ntp * 16 + (lane & 7) + (((lane >> 4) & 1) << 3)) * ASH +
                                      ks * 16 + (((lane >> 3) & 1) << 3)]));
                mma_f16(s[2 * ntp], qfr[ks], t0, t1);
                mma_f16(s[2 * ntp + 1], qfr[ks], t2, t3);
            }
        }

        // biasM add (k-mask + scale pre-folded) + q-mask + online softmax
        float rmax0 = -1e30f, rmax1 = -1e30f;
#pragma unroll
        for (int nt = 0; nt < 8; nt++) {
            float2 f0 = __half22float2(bb0[nt]);
            float2 f1 = __half22float2(bb1[nt]);
            float v0 = mq0 ? (s[nt][0] + f0.x) : 0.f;
            float v1 = mq0 ? (s[nt][1] + f0.y) : 0.f;
            float v2 = mq1 ? (s[nt][2] + f1.x) : 0.f;
            float v3 = mq1 ? (s[nt][3] + f1.y) : 0.f;
            s[nt][0] = v0; s[nt][1] = v1; s[nt][2] = v2; s[nt][3] = v3;
            rmax0 = fmaxf(rmax0, fmaxf(v0, v1));
            rmax1 = fmaxf(rmax1, fmaxf(v2, v3));
        }
        rmax0 = fmaxf(rmax0, __shfl_xor_sync(0xffffffffu, rmax0, 1));
        rmax0 = fmaxf(rmax0, __shfl_xor_sync(0xffffffffu, rmax0, 2));
        rmax1 = fmaxf(rmax1, __shfl_xor_sync(0xffffffffu, rmax1, 1));
        rmax1 = fmaxf(rmax1, __shfl_xor_sync(0xffffffffu, rmax1, 2));

        float mnew0 = fmaxf(mrow0, rmax0), mnew1 = fmaxf(mrow1, rmax1);
        float alpha0 = __expf(mrow0 - mnew0), alpha1 = __expf(mrow1 - mnew1);
        mrow0 = mnew0; mrow1 = mnew1;

        float sum0 = 0.f, sum1 = 0.f;
#pragma unroll
        for (int nt = 0; nt < 8; nt++) {
            s[nt][0] = __expf(s[nt][0] - mnew0); sum0 += s[nt][0];
            s[nt][1] = __expf(s[nt][1] - mnew0); sum0 += s[nt][1];
            s[nt][2] = __expf(s[nt][2] - mnew1); sum1 += s[nt][2];
            s[nt][3] = __expf(s[nt][3] - mnew1); sum1 += s[nt][3];
        }
        sum0 += __shfl_xor_sync(0xffffffffu, sum0, 1);
        sum0 += __shfl_xor_sync(0xffffffffu, sum0, 2);
        sum1 += __shfl_xor_sync(0xffffffffu, sum1, 1);
        sum1 += __shfl_xor_sync(0xffffffffu, sum1, 2);
        lrow0 = lrow0 * alpha0 + sum0;
        lrow1 = lrow1 * alpha1 + sum1;

#pragma unroll
        for (int nt = 0; nt < 8; nt++) {
            o[nt][0] *= alpha0; o[nt][1] *= alpha0;
            o[nt][2] *= alpha1; o[nt][3] *= alpha1;
        }

        // O += P V — P packed straight from the S accumulators
#pragma unroll
        for (int ks = 0; ks < 4; ks++) {
            unsigned ap[4];
            ap[0] = h2u(__floats2half2_rn(s[2 * ks][0], s[2 * ks][1]));
            ap[1] = h2u(__floats2half2_rn(s[2 * ks][2], s[2 * ks][3]));
            ap[2] = h2u(__floats2half2_rn(s[2 * ks + 1][0], s[2 * ks + 1][1]));
            ap[3] = h2u(__floats2half2_rn(s[2 * ks + 1][2], s[2 * ks + 1][3]));
#pragma unroll
            for (int ntp = 0; ntp < 4; ntp++) {
                unsigned t0, t1, t2, t3;
                ldsm4t(t0, t1, t2, t3,
                       smaddr(&sV[buf][(ks * 16 + (lane & 7) + (((lane >> 3) & 1) << 3)) * ASH +
                                       ntp * 16 + (((lane >> 4) & 1) << 3)]));
                mma_f16(o[2 * ntp], ap, t0, t1);
                mma_f16(o[2 * ntp + 1], ap, t2, t3);
            }
        }
    }

    // Epilogue: normalize, write ctx fp16 [B,S,D]
    float inv0 = 1.f / lrow0, inv1 = 1.f / lrow1;
    __half* Cg = g_ctx + ((size_t)b * Sn + q0) * Dn + h * DKn;
#pragma unroll
    for (int nt = 0; nt < 8; nt++) {
        int col = nt * 8 + ((lane & 3) << 1);
        *(__half2*)(Cg + (size_t)rq * Dn + col) =
            __floats2half2_rn(o[nt][0] * inv0, o[nt][1] * inv0);
        *(__half2*)(Cg + (size_t)(rq + 8) * Dn + col) =
            __floats2half2_rn(o[nt][2] * inv1, o[nt][3] * inv1);
    }
}

// ---------------------------------------------------------------------------
// kernel_launch
// ---------------------------------------------------------------------------
extern "C" void kernel_launch(void* const* d_in, const int* in_sizes, int n_in,
                              void* d_out, int out_size) {
    (void)in_sizes; (void)n_in; (void)out_size;
    const float* query = (const float*)d_in[0];
    const float* key   = (const float*)d_in[1];
    const float* value = (const float*)d_in[2];
    const float* bias  = (const float*)d_in[3];
    const void*  mask  = d_in[4];
    const float* Wq = (const float*)d_in[5];
    const float* bq = (const float*)d_in[6];
    const float* Wk = (const float*)d_in[7];
    const float* bk = (const float*)d_in[8];
    const float* Wv = (const float*)d_in[9];
    const float* bv = (const float*)d_in[10];
    const float* Wo = (const float*)d_in[11];
    const float* bo = (const float*)d_in[12];
    float* out = (float*)d_out;

    f2h_kernel<<<dim3(1024, 1, 8), 256>>>(query, key, value, Wq, Wk, Wv, Wo, mask);
    bias_tr_kernel<<<dim3(Sn / 128, Sn, Bn), 256>>>(bias);
    qkv_proj_kernel<<<dim3(Dn / 128, (Bn * Sn) / 128, 3), 256>>>(bq, bk, bv);
    attn_kernel<<<dim3(Sn / 64, Hn, Bn), 128>>>();
    outproj_kernel<<<dim3(Dn / 128, (Bn * Sn) / 128, 1), 256>>>(bo, out);
}

// round 17
// speedup vs baseline: 1.0163x; 1.0163x over previous
#include <cuda_runtime.h>
#include <cuda_fp16.h>

// ---------------------------------------------------------------------------
// Problem constants
// ---------------------------------------------------------------------------
#define Bn  4
#define Sn  1024
#define Dn  1024
#define Hn  16
#define DKn 64

// ---------------------------------------------------------------------------
// Device scratch (everything on the mma path stored fp16)
// ---------------------------------------------------------------------------
__device__ __half g_q[(size_t)Bn * Hn * Sn * DKn];     // [B,H,S,DK] (pre-scaled by 0.125)
__device__ __half g_k[(size_t)Bn * Hn * Sn * DKn];
__device__ __half g_v[(size_t)Bn * Hn * Sn * DKn];
__device__ __half g_biasT[(size_t)Bn * Hn * Sn * Sn];  // [B,H,S,S] fp16, mask+scale folded
__device__ __half g_ctx[(size_t)Bn * Sn * Dn];         // [B,S,D] fp16
__device__ __half g_xq[(size_t)Bn * Sn * Dn];          // fp16 inputs
__device__ __half g_xk[(size_t)Bn * Sn * Dn];
__device__ __half g_xv[(size_t)Bn * Sn * Dn];
__device__ __half g_wq[(size_t)Dn * Dn];               // fp16 weights
__device__ __half g_wk[(size_t)Dn * Dn];
__device__ __half g_wv[(size_t)Dn * Dn];
__device__ __half g_wo[(size_t)Dn * Dn];
__device__ unsigned char g_mask[Bn * Sn];

// ---------------------------------------------------------------------------
// Helpers
// ---------------------------------------------------------------------------
__device__ __forceinline__ unsigned h2u(__half2 h) {
    return *reinterpret_cast<unsigned*>(&h);
}

__device__ __forceinline__ unsigned smaddr(const void* p) {
    return (unsigned)__cvta_generic_to_shared(p);
}

__device__ __forceinline__ void ldsm4(unsigned& r0, unsigned& r1, unsigned& r2,
                                      unsigned& r3, unsigned addr) {
    asm volatile("ldmatrix.sync.aligned.m8n8.x4.shared.b16 {%0,%1,%2,%3}, [%4];"
                 : "=r"(r0), "=r"(r1), "=r"(r2), "=r"(r3) : "r"(addr));
}

__device__ __forceinline__ void ldsm4t(unsigned& r0, unsigned& r1, unsigned& r2,
                                       unsigned& r3, unsigned addr) {
    asm volatile("ldmatrix.sync.aligned.m8n8.x4.trans.shared.b16 {%0,%1,%2,%3}, [%4];"
                 : "=r"(r0), "=r"(r1), "=r"(r2), "=r"(r3) : "r"(addr));
}

__device__ __forceinline__ void mma_f16(float c[4], const unsigned a[4],
                                        unsigned b0, unsigned b1) {
    asm volatile(
        "mma.sync.aligned.m16n8k16.row.col.f32.f16.f16.f32 "
        "{%0,%1,%2,%3},{%4,%5,%6,%7},{%8,%9},{%0,%1,%2,%3};\n"
        : "+f"(c[0]), "+f"(c[1]), "+f"(c[2]), "+f"(c[3])
        : "r"(a[0]), "r"(a[1]), "r"(a[2]), "r"(a[3]), "r"(b0), "r"(b1));
}

__device__ __forceinline__ void cpa16(unsigned dst, const void* src) {
    asm volatile("cp.async.cg.shared.global [%0], [%1], 16;"
                 :: "r"(dst), "l"(src) : "memory");
}

#define CPA_COMMIT() asm volatile("cp.async.commit_group;" ::: "memory")
#define CPA_WAIT(n)  asm volatile("cp.async.wait_group %0;" :: "n"(n) : "memory")

// ---------------------------------------------------------------------------
// fp32 -> fp16 conversion for inputs + weights; z==7 also normalizes the mask
// ---------------------------------------------------------------------------
__global__ void f2h_kernel(const float* __restrict__ xq, const float* __restrict__ xk,
                           const float* __restrict__ xv, const float* __restrict__ wq,
                           const float* __restrict__ wk, const float* __restrict__ wv,
                           const float* __restrict__ wo, const void* __restrict__ mraw) {
    int z = blockIdx.z;
    if (z == 7) {
        if (blockIdx.x != 0) return;
        __shared__ int flags[2];
        if (threadIdx.x < 2) flags[threadIdx.x] = 0;
        __syncthreads();
        const unsigned* w = (const unsigned*)mraw;
        for (int i = threadIdx.x; i < 1024; i += blockDim.x) {
            unsigned v = w[i];
            if (v > 1u) flags[0] = 1;
            if (v != 0u && v != 0x3F800000u) flags[1] = 1;
        }
        __syncthreads();
        int mode = flags[0] ? (flags[1] ? 0 : 2) : 1;
        for (int i = threadIdx.x; i < Bn * Sn; i += blockDim.x) {
            unsigned char v;
            if (mode == 1)      v = (((const int*)mraw)[i] != 0);
            else if (mode == 2) v = (((const float*)mraw)[i] != 0.f);
            else                v = (((const unsigned char*)mraw)[i] != 0);
            g_mask[i] = v;
        }
        return;
    }
    const float* src;
    __half* dst;
    int n4;
    switch (z) {
        case 0: src = xq; dst = g_xq; n4 = (Bn * Sn * Dn) / 4; break;
        case 1: src = xk; dst = g_xk; n4 = (Bn * Sn * Dn) / 4; break;
        case 2: src = xv; dst = g_xv; n4 = (Bn * Sn * Dn) / 4; break;
        case 3: src = wq; dst = g_wq; n4 = (Dn * Dn) / 4; break;
        case 4: src = wk; dst = g_wk; n4 = (Dn * Dn) / 4; break;
        case 5: src = wv; dst = g_wv; n4 = (Dn * Dn) / 4; break;
        default: src = wo; dst = g_wo; n4 = (Dn * Dn) / 4; break;
    }
    for (int i = blockIdx.x * blockDim.x + threadIdx.x; i < n4;
         i += gridDim.x * blockDim.x) {
        float4 v = ((const float4*)src)[i];
        ((uint2*)dst)[i] = make_uint2(h2u(__floats2half2_rn(v.x, v.y)),
                                      h2u(__floats2half2_rn(v.z, v.w)));
    }
}

// ---------------------------------------------------------------------------
// Bias transpose [B,S,S,H] fp32 -> [B,H,S,S] fp16, with the k-mask and the
// 1/sqrt(dk)=0.125 scale folded in:
//   biasM[b,h,q,k] = maskK[b,k] ? bias*0.125 : -30000
// Mask bytes for this CTA's 128-k block staged ONCE into shared (coalesced);
// the per-element fold reads smem, keeping the kernel DRAM-bound.
// Runs after f2h (g_mask ready).
// ---------------------------------------------------------------------------
__global__ void bias_tr_kernel(const float* __restrict__ bias) {
    __shared__ float t[16][129];
    __shared__ unsigned char smkb[128];
    const int k0 = blockIdx.x * 128;
    const int q  = blockIdx.y;
    const int b  = blockIdx.z;
    const float* src = bias + ((size_t)(b * Sn + q) * Sn + k0) * Hn;
    if (threadIdx.x < 128) smkb[threadIdx.x] = g_mask[b * Sn + k0 + threadIdx.x];
    for (int i = threadIdx.x; i < 2048; i += 256) {
        int kk = i >> 4, hh = i & 15;
        t[hh][kk] = __ldcs(src + i);
    }
    __syncthreads();
    for (int i = threadIdx.x; i < 1024; i += 256) {
        int hh = i >> 6, kk2 = i & 63;
        int kl = kk2 * 2;
        float v0 = smkb[kl]     ? t[hh][kl] * 0.125f     : -30000.f;
        float v1 = smkb[kl + 1] ? t[hh][kl + 1] * 0.125f : -30000.f;
        __half2 v = __floats2half2_rn(v0, v1);
        __half* dst = &g_biasT[((size_t)(b * Hn + hh) * Sn + q) * Sn + k0 + kl];
        __stcs((__half2*)dst, v);
    }
}

// ---------------------------------------------------------------------------
// TN GEMM fp16 (R15): 128x128x32 tile, 256 threads, 8 warps (2m x 4n),
// 2-stage cp.async pipeline, ONE __syncthreads per k-tile.
// oscale multiplies the final (acc + bias) — used to pre-scale Q by 0.125.
// ---------------------------------------------------------------------------
#define GSH 40   // smem stride in halves (80B rows: ldmatrix conflict-free)

template <int MODE>
__device__ __forceinline__ void gemm_h16(const __half* __restrict__ A,
                                         const __half* __restrict__ W,
                                         const float* __restrict__ bvec,
                                         void* __restrict__ outv,
                                         float oscale) {
    __shared__ __half sA[2][128 * GSH];
    __shared__ __half sW[2][128 * GSH];

    const int tid  = threadIdx.x;
    const int lane = tid & 31;
    const int warp = tid >> 5;
    const int wm = (warp >> 2) * 64;
    const int wn = (warp & 3) * 32;
    const int m0 = blockIdx.y * 128;
    const int n0 = blockIdx.x * 128;

    float acc[4][4][4];
#pragma unroll
    for (int mt = 0; mt < 4; mt++)
#pragma unroll
        for (int nt = 0; nt < 4; nt++)
#pragma unroll
            for (int q = 0; q < 4; q++) acc[mt][nt][q] = 0.f;

#pragma unroll
    for (int i = 0; i < 2; i++) {
        int task = i * 256 + tid;
        int row = task >> 2, c8 = task & 3;
        cpa16(smaddr(&sA[0][row * GSH + c8 * 8]), A + (size_t)(m0 + row) * Dn + c8 * 8);
        cpa16(smaddr(&sW[0][row * GSH + c8 * 8]), W + (size_t)(n0 + row) * Dn + c8 * 8);
    }
    CPA_COMMIT();

    for (int kt = 0; kt < 32; kt++) {
        const int b = kt & 1;
        CPA_WAIT(0);
        __syncthreads();

        if (kt < 31) {
            const int kb = (kt + 1) * 32;
#pragma unroll
            for (int i = 0; i < 2; i++) {
                int task = i * 256 + tid;
                int row = task >> 2, c8 = task & 3;
                cpa16(smaddr(&sA[b ^ 1][row * GSH + c8 * 8]),
                      A + (size_t)(m0 + row) * Dn + kb + c8 * 8);
                cpa16(smaddr(&sW[b ^ 1][row * GSH + c8 * 8]),
                      W + (size_t)(n0 + row) * Dn + kb + c8 * 8);
            }
            CPA_COMMIT();
        }

        const __half* cA = sA[b];
        const __half* cW = sW[b];
#pragma unroll
        for (int ks = 0; ks < 2; ks++) {
            const int koff = ks * 16 + ((lane >> 4) << 3);
            unsigned afr[4][4];
#pragma unroll
            for (int mt = 0; mt < 4; mt++)
                ldsm4(afr[mt][0], afr[mt][1], afr[mt][2], afr[mt][3],
                      smaddr(&cA[(wm + mt * 16 + (lane & 15)) * GSH + koff]));
            unsigned bfr[4][2];
#pragma unroll
            for (int ntp = 0; ntp < 2; ntp++) {
                unsigned t0, t1, t2, t3;
                ldsm4(t0, t1, t2, t3,
                      smaddr(&cW[(wn + ntp * 16 + (lane & 7) + (((lane >> 4) & 1) << 3)) * GSH +
                                 ks * 16 + (((lane >> 3) & 1) << 3)]));
                bfr[2 * ntp][0] = t0; bfr[2 * ntp][1] = t1;
                bfr[2 * ntp + 1][0] = t2; bfr[2 * ntp + 1][1] = t3;
            }
#pragma unroll
            for (int mt = 0; mt < 4; mt++)
#pragma unroll
                for (int nt = 0; nt < 4; nt++)
                    mma_f16(acc[mt][nt], afr[mt], bfr[nt][0], bfr[nt][1]);
        }
    }

#pragma unroll
    for (int mt = 0; mt < 4; mt++) {
#pragma unroll
        for (int nt = 0; nt < 4; nt++) {
            int row = m0 + wm + mt * 16 + (lane >> 2);
            int col = n0 + wn + nt * 8 + ((lane & 3) << 1);
            float b0 = bvec[col], b1 = bvec[col + 1];
            float v00 = (acc[mt][nt][0] + b0) * oscale, v01 = (acc[mt][nt][1] + b1) * oscale;
            float v10 = (acc[mt][nt][2] + b0) * oscale, v11 = (acc[mt][nt][3] + b1) * oscale;
            if (MODE == 0) {
                float* out = (float*)outv;
                *(float2*)(out + (size_t)row * Dn + col) = make_float2(v00, v01);
                *(float2*)(out + (size_t)(row + 8) * Dn + col) = make_float2(v10, v11);
            } else {
                __half* out = (__half*)outv;
                int hh = col >> 6, dk = col & 63;
                int bb0 = row >> 10, s0 = row & 1023;
                int r8 = row + 8;
                int bb1 = r8 >> 10, s1 = r8 & 1023;
                *(__half2*)(out + ((size_t)(bb0 * Hn + hh) * Sn + s0) * DKn + dk) =
                    __floats2half2_rn(v00, v01);
                *(__half2*)(out + ((size_t)(bb1 * Hn + hh) * Sn + s1) * DKn + dk) =
                    __floats2half2_rn(v10, v11);
            }
        }
    }
}

__global__ void __launch_bounds__(256) qkv_proj_kernel(
    const float* __restrict__ bq, const float* __restrict__ bk,
    const float* __restrict__ bv) {
    int z = blockIdx.z;
    const __half* A = (z == 0) ? g_xq : (z == 1) ? g_xk : g_xv;
    const __half* W = (z == 0) ? g_wq : (z == 1) ? g_wk : g_wv;
    const float* bb = (z == 0) ? bq : (z == 1) ? bk : bv;
    __half* out = (z == 0) ? g_q : (z == 1) ? g_k : g_v;
    gemm_h16<1>(A, W, bb, out, (z == 0) ? 0.125f : 1.0f);
}

__global__ void __launch_bounds__(256) outproj_kernel(
    const float* __restrict__ bo, float* __restrict__ out) {
    gemm_h16<0>(g_ctx, g_wo, bo, out, 1.0f);
}

// ---------------------------------------------------------------------------
// Flash attention fp16 (R16 known-good): 64 q-rows, 128 threads, 3 CTAs/SM.
//  - Q frags hoisted; P in registers (FA2); K/V cp.async double-buffered
//  - scale + k-mask pre-folded into Q / biasM: hot loop is v = mq ? s+b : 0
// ---------------------------------------------------------------------------
#define ASH 72   // smem stride in halves (144B rows: ldmatrix conflict-free)

__global__ void __launch_bounds__(128, 3) attn_kernel() {
    __shared__ __half sQ[64 * ASH];
    __shared__ __half sK[2][64 * ASH];
    __shared__ __half sV[2][64 * ASH];

    const int qt = blockIdx.x, h = blockIdx.y, b = blockIdx.z;
    const int q0 = qt * 64;
    const int tid = threadIdx.x, lane = tid & 31, warp = tid >> 5;
    const int rq = warp * 16 + (lane >> 2);

    const size_t headoff = (size_t)(b * Hn + h) * Sn * DKn;
    const __half* Qg = g_q + headoff + (size_t)q0 * DKn;
    const __half* Kg = g_k + headoff;
    const __half* Vg = g_v + headoff;
    const __half* Bg = g_biasT + ((size_t)(b * Hn + h) * Sn + q0) * Sn;
    const unsigned char* Mg = g_mask + b * Sn;

#pragma unroll
    for (int i = 0; i < 4; i++) {
        int task = i * 128 + tid;
        int row = task >> 3, c4 = task & 7;
        *(uint4*)&sQ[row * ASH + c4 * 8] = *(const uint4*)(Qg + (size_t)row * DKn + c4 * 8);
        cpa16(smaddr(&sK[0][row * ASH + c4 * 8]), Kg + (size_t)row * DKn + c4 * 8);
        cpa16(smaddr(&sV[0][row * ASH + c4 * 8]), Vg + (size_t)row * DKn + c4 * 8);
    }
    CPA_COMMIT();
    __syncthreads();
    unsigned qfr[4][4];
#pragma unroll
    for (int ks = 0; ks < 4; ks++)
        ldsm4(qfr[ks][0], qfr[ks][1], qfr[ks][2], qfr[ks][3],
              smaddr(&sQ[(warp * 16 + (lane & 15)) * ASH + ks * 16 + ((lane >> 4) << 3)]));

    const int mq0 = Mg[q0 + rq];
    const int mq1 = Mg[q0 + rq + 8];

    float mrow0 = -1e30f, mrow1 = -1e30f, lrow0 = 0.f, lrow1 = 0.f;
    float o[8][4];
#pragma unroll
    for (int nt = 0; nt < 8; nt++)
#pragma unroll
        for (int q = 0; q < 4; q++) o[nt][q] = 0.f;

    for (int kt = 0; kt < 16; kt++) {
        const int kv0 = kt * 64;
        const int buf = kt & 1;

        __half2 bb0[8], bb1[8];
#pragma unroll
        for (int nt = 0; nt < 8; nt++) {
            int col = kv0 + nt * 8 + ((lane & 3) << 1);
            bb0[nt] = __ldcs((const __half2*)(Bg + (size_t)rq * Sn + col));
            bb1[nt] = __ldcs((const __half2*)(Bg + (size_t)(rq + 8) * Sn + col));
        }

        CPA_WAIT(0);
        __syncthreads();  // tile kt resident; reads of buf^1 (kt-1) retired

        if (kt < 15) {
            const int kb = kv0 + 64;
#pragma unroll
            for (int i = 0; i < 4; i++) {
                int task = i * 128 + tid;
                int row = task >> 3, c4 = task & 7;
                cpa16(smaddr(&sK[buf ^ 1][row * ASH + c4 * 8]),
                      Kg + (size_t)(kb + row) * DKn + c4 * 8);
                cpa16(smaddr(&sV[buf ^ 1][row * ASH + c4 * 8]),
                      Vg + (size_t)(kb + row) * DKn + c4 * 8);
            }
            CPA_COMMIT();
        }

        // S = Q K^T  (Q pre-scaled by 0.125)
        float s[8][4];
#pragma unroll
        for (int nt = 0; nt < 8; nt++)
#pragma unroll
            for (int q = 0; q < 4; q++) s[nt][q] = 0.f;

#pragma unroll
        for (int ks = 0; ks < 4; ks++) {
#pragma unroll
            for (int ntp = 0; ntp < 4; ntp++) {
                unsigned t0, t1, t2, t3;
                ldsm4(t0, t1, t2, t3,
                      smaddr(&sK[buf][(ntp * 16 + (lane & 7) + (((lane >> 4) & 1) << 3)) * ASH +
                                      ks * 16 + (((lane >> 3) & 1) << 3)]));
                mma_f16(s[2 * ntp], qfr[ks], t0, t1);
                mma_f16(s[2 * ntp + 1], qfr[ks], t2, t3);
            }
        }

        // biasM add (k-mask + scale pre-folded) + q-mask + online softmax
        float rmax0 = -1e30f, rmax1 = -1e30f;
#pragma unroll
        for (int nt = 0; nt < 8; nt++) {
            float2 f0 = __half22float2(bb0[nt]);
            float2 f1 = __half22float2(bb1[nt]);
            float v0 = mq0 ? (s[nt][0] + f0.x) : 0.f;
            float v1 = mq0 ? (s[nt][1] + f0.y) : 0.f;
            float v2 = mq1 ? (s[nt][2] + f1.x) : 0.f;
            float v3 = mq1 ? (s[nt][3] + f1.y) : 0.f;
            s[nt][0] = v0; s[nt][1] = v1; s[nt][2] = v2; s[nt][3] = v3;
            rmax0 = fmaxf(rmax0, fmaxf(v0, v1));
            rmax1 = fmaxf(rmax1, fmaxf(v2, v3));
        }
        rmax0 = fmaxf(rmax0, __shfl_xor_sync(0xffffffffu, rmax0, 1));
        rmax0 = fmaxf(rmax0, __shfl_xor_sync(0xffffffffu, rmax0, 2));
        rmax1 = fmaxf(rmax1, __shfl_xor_sync(0xffffffffu, rmax1, 1));
        rmax1 = fmaxf(rmax1, __shfl_xor_sync(0xffffffffu, rmax1, 2));

        float mnew0 = fmaxf(mrow0, rmax0), mnew1 = fmaxf(mrow1, rmax1);
        float alpha0 = __expf(mrow0 - mnew0), alpha1 = __expf(mrow1 - mnew1);
        mrow0 = mnew0; mrow1 = mnew1;

        float sum0 = 0.f, sum1 = 0.f;
#pragma unroll
        for (int nt = 0; nt < 8; nt++) {
            s[nt][0] = __expf(s[nt][0] - mnew0); sum0 += s[nt][0];
            s[nt][1] = __expf(s[nt][1] - mnew0); sum0 += s[nt][1];
            s[nt][2] = __expf(s[nt][2] - mnew1); sum1 += s[nt][2];
            s[nt][3] = __expf(s[nt][3] - mnew1); sum1 += s[nt][3];
        }
        sum0 += __shfl_xor_sync(0xffffffffu, sum0, 1);
        sum0 += __shfl_xor_sync(0xffffffffu, sum0, 2);
        sum1 += __shfl_xor_sync(0xffffffffu, sum1, 1);
        sum1 += __shfl_xor_sync(0xffffffffu, sum1, 2);
        lrow0 = lrow0 * alpha0 + sum0;
        lrow1 = lrow1 * alpha1 + sum1;

#pragma unroll
        for (int nt = 0; nt < 8; nt++) {
            o[nt][0] *= alpha0; o[nt][1] *= alpha0;
            o[nt][2] *= alpha1; o[nt][3] *= alpha1;
        }

        // O += P V — P packed straight from the S accumulators
#pragma unroll
        for (int ks = 0; ks < 4; ks++) {
            unsigned ap[4];
            ap[0] = h2u(__floats2half2_rn(s[2 * ks][0], s[2 * ks][1]));
            ap[1] = h2u(__floats2half2_rn(s[2 * ks][2], s[2 * ks][3]));
            ap[2] = h2u(__floats2half2_rn(s[2 * ks + 1][0], s[2 * ks + 1][1]));
            ap[3] = h2u(__floats2half2_rn(s[2 * ks + 1][2], s[2 * ks + 1][3]));
#pragma unroll
            for (int ntp = 0; ntp < 4; ntp++) {
                unsigned t0, t1, t2, t3;
                ldsm4t(t0, t1, t2, t3,
                       smaddr(&sV[buf][(ks * 16 + (lane & 7) + (((lane >> 3) & 1) << 3)) * ASH +
                                       ntp * 16 + (((lane >> 4) & 1) << 3)]));
                mma_f16(o[2 * ntp], ap, t0, t1);
                mma_f16(o[2 * ntp + 1], ap, t2, t3);
            }
        }
    }

    // Epilogue: normalize, write ctx fp16 [B,S,D]
    float inv0 = 1.f / lrow0, inv1 = 1.f / lrow1;
    __half* Cg = g_ctx + ((size_t)b * Sn + q0) * Dn + h * DKn;
#pragma unroll
    for (int nt = 0; nt < 8; nt++) {
        int col = nt * 8 + ((lane & 3) << 1);
        *(__half2*)(Cg + (size_t)rq * Dn + col) =
            __floats2half2_rn(o[nt][0] * inv0, o[nt][1] * inv0);
        *(__half2*)(Cg + (size_t)(rq + 8) * Dn + col) =
            __floats2half2_rn(o[nt][2] * inv1, o[nt][3] * inv1);
    }
}

// ---------------------------------------------------------------------------
// kernel_launch
// ---------------------------------------------------------------------------
extern "C" void kernel_launch(void* const* d_in, const int* in_sizes, int n_in,
                              void* d_out, int out_size) {
    (void)in_sizes; (void)n_in; (void)out_size;
    const float* query = (const float*)d_in[0];
    const float* key   = (const float*)d_in[1];
    const float* value = (const float*)d_in[2];
    const float* bias  = (const float*)d_in[3];
    const void*  mask  = d_in[4];
    const float* Wq = (const float*)d_in[5];
    const float* bq = (const float*)d_in[6];
    const float* Wk = (const float*)d_in[7];
    const float* bk = (const float*)d_in[8];
    const float* Wv = (const float*)d_in[9];
    const float* bv = (const float*)d_in[10];
    const float* Wo = (const float*)d_in[11];
    const float* bo = (const float*)d_in[12];
    float* out = (float*)d_out;

    f2h_kernel<<<dim3(1024, 1, 8), 256>>>(query, key, value, Wq, Wk, Wv, Wo, mask);
    bias_tr_kernel<<<dim3(Sn / 128, Sn, Bn), 256>>>(bias);
    qkv_proj_kernel<<<dim3(Dn / 128, (Bn * Sn) / 128, 3), 256>>>(bq, bk, bv);
    attn_kernel<<<dim3(Sn / 64, Hn, Bn), 128>>>();
    outproj_kernel<<<dim3(Dn / 128, (Bn * Sn) / 128, 1), 256>>>(bo, out);
}